// round 3
// baseline (speedup 1.0000x reference)
#include <cuda_runtime.h>
#include <math.h>

// ---------------------------------------------------------------------------
// Static device scratch (ping-pong A/B + persistent skip buffers).
//   A max use: cat2 = 4*384*128*128 = 25,165,824 floats
//   B max use: cat1 = 4*160*256*256 = 41,943,040 floats
// ---------------------------------------------------------------------------
__device__ float g_SA[25165824];
__device__ float g_SB[41943040];
__device__ float g_C1[8388608];   // (4,32,256,256)
__device__ float g_C2[8388608];   // (4,128,128,128)
__device__ float g_C3[4194304];   // (4,256,64,64)
__device__ float g_BNscale[512];
__device__ float g_BNshift[512];

static inline int cdiv(int a, int b) { return (a + b - 1) / b; }

__device__ __forceinline__ float mishf(float x) {
    // x * tanh(softplus(x)), cancellation-safe softplus
    float sp = fmaxf(x, 0.f) + log1pf(expf(-fabsf(x)));
    return x * tanhf(sp);
}

// ---------------------------------------------------------------------------
// Generic direct conv + bias + mish.
// Block: 128 threads -> 32 output channels x (8 rows x 16 cols) tile, one batch.
// Requires: Ci % 8 == 0, Co % 32 == 0, Ho % 8 == 0, Wo % 16 == 0 (all layers OK).
// Input loads are guarded (handles zero padding and Hi=Wi=255 case).
// ---------------------------------------------------------------------------
template<int K>
__global__ __launch_bounds__(128)
void conv_mish_kernel(const float* __restrict__ in, const float* __restrict__ wt,
                      const float* __restrict__ bias, float* __restrict__ out,
                      int Ci, int Hi, int Wi, int Co, int Ho, int Wo, int pad)
{
    constexpr int K2    = K * K;
    constexpr int CI_CH = 8;
    constexpr int CO_T  = 32;
    constexpr int TH    = 8;
    constexpr int TW    = 16;
    constexpr int XH    = TH + K - 1;
    constexpr int XW    = TW + K - 1;
    constexpr int PER   = CI_CH * K2;      // floats per co in weight chunk

    __shared__ float ws[CO_T * PER];
    __shared__ float xs[CI_CH * XH * XW];

    const int b   = blockIdx.z;
    const int co0 = blockIdx.y * CO_T;
    const int ntx = Wo / TW;
    const int ty  = blockIdx.x / ntx;
    const int tx  = blockIdx.x - ty * ntx;
    const int y0  = ty * TH;
    const int x0  = tx * TW;

    const int tid = threadIdx.x;
    const int cog = tid >> 4;              // 0..7 -> co_local = cog*4
    const int pg  = tid & 15;              // pixel group
    const int r   = pg >> 1;               // row within tile (0..7)
    const int c0  = (pg & 1) * 8;          // col base within tile (0 or 8)

    float acc[4][8];
#pragma unroll
    for (int a = 0; a < 4; a++)
#pragma unroll
        for (int p = 0; p < 8; p++) acc[a][p] = 0.f;

    const float* inb = in + (size_t)b * Ci * Hi * Wi;

    for (int ci0 = 0; ci0 < Ci; ci0 += CI_CH) {
        // weights chunk: smem layout [co_local][ci][ij] == contiguous slice of global
        for (int idx = tid; idx < CO_T * PER; idx += 128) {
            int co  = idx / PER;
            int rem = idx - co * PER;      // ci*K2 + ij
            ws[idx] = wt[(size_t)(co0 + co) * Ci * K2 + (size_t)ci0 * K2 + rem];
        }
        // input tile with halo
        for (int idx = tid; idx < CI_CH * XH * XW; idx += 128) {
            int ci  = idx / (XH * XW);
            int rem = idx - ci * (XH * XW);
            int yy  = rem / XW;
            int xx  = rem - yy * XW;
            int gy  = y0 - pad + yy;
            int gx  = x0 - pad + xx;
            float v = 0.f;
            if (gy >= 0 && gy < Hi && gx >= 0 && gx < Wi)
                v = inb[(size_t)(ci0 + ci) * Hi * Wi + (size_t)gy * Wi + gx];
            xs[idx] = v;
        }
        __syncthreads();

#pragma unroll
        for (int ci = 0; ci < CI_CH; ci++) {
            const float* wb = &ws[(cog * 4) * PER + ci * K2];
            const float* xb = &xs[ci * XH * XW];
#pragma unroll
            for (int i = 0; i < K; i++) {
                float xr[8 + K - 1];
                const float* xp = xb + (r + i) * XW + c0;
#pragma unroll
                for (int t = 0; t < 8 + K - 1; t++) xr[t] = xp[t];
#pragma unroll
                for (int j = 0; j < K; j++) {
                    float w0 = wb[i * K + j];
                    float w1 = wb[PER     + i * K + j];
                    float w2 = wb[2 * PER + i * K + j];
                    float w3 = wb[3 * PER + i * K + j];
#pragma unroll
                    for (int p = 0; p < 8; p++) {
                        float xv = xr[j + p];
                        acc[0][p] = fmaf(w0, xv, acc[0][p]);
                        acc[1][p] = fmaf(w1, xv, acc[1][p]);
                        acc[2][p] = fmaf(w2, xv, acc[2][p]);
                        acc[3][p] = fmaf(w3, xv, acc[3][p]);
                    }
                }
            }
        }
        __syncthreads();
    }

#pragma unroll
    for (int a = 0; a < 4; a++) {
        int co   = co0 + cog * 4 + a;
        float bv = bias[co];
        float* op = out + ((size_t)b * Co + co) * Ho * Wo
                        + (size_t)(y0 + r) * Wo + x0 + c0;
#pragma unroll
        for (int p = 0; p < 8; p++)
            op[p] = mishf(acc[a][p] + bv);
    }
}

// ---------------------------------------------------------------------------
// Per-sample dynamic conv (Ci=1, K=4, pad=1) + mish. x:(4,1,256,256),
// w:(4,32,4,4) -> out:(4,32,255,255). Block: 16x16 spatial tile, all 32 co.
// ---------------------------------------------------------------------------
__global__ __launch_bounds__(256)
void dyn_conv_mish(const float* __restrict__ x, const float* __restrict__ w,
                   float* __restrict__ out)
{
    const int H = 256, HO = 255;
    __shared__ float ws[32 * 16];
    __shared__ float xs[19][19];

    int b  = blockIdx.z;
    int y0 = blockIdx.y * 16;
    int x0 = blockIdx.x * 16;
    int tid = threadIdx.x;

    for (int i = tid; i < 512; i += 256) ws[i] = w[b * 512 + i];
    for (int i = tid; i < 19 * 19; i += 256) {
        int yy = i / 19, xx = i - yy * 19;
        int gy = y0 - 1 + yy, gx = x0 - 1 + xx;
        xs[yy][xx] = (gy >= 0 && gy < H && gx >= 0 && gx < H)
                     ? x[(size_t)b * H * H + (size_t)gy * H + gx] : 0.f;
    }
    __syncthreads();

    int r  = tid >> 4;
    int cl = tid & 15;
    int oy = y0 + r, ox = x0 + cl;
    if (oy >= HO || ox >= HO) return;

    float xr[16];
#pragma unroll
    for (int i = 0; i < 4; i++)
#pragma unroll
        for (int j = 0; j < 4; j++) xr[i * 4 + j] = xs[r + i][cl + j];

    float* op = out + (size_t)b * 32 * HO * HO + (size_t)oy * HO + ox;
#pragma unroll
    for (int co = 0; co < 32; co++) {
        float a = 0.f;
#pragma unroll
        for (int t = 0; t < 16; t++) a = fmaf(xr[t], ws[co * 16 + t], a);
        op[(size_t)co * HO * HO] = mishf(a);
    }
}

// ---------------------------------------------------------------------------
__global__ void maxpool_kernel(const float* __restrict__ in, float* __restrict__ out,
                               int BC, int Hi, int Wi)
{
    int Ho = Hi >> 1, Wo = Wi >> 1;
    int total = BC * Ho * Wo;
    int n = blockIdx.x * blockDim.x + threadIdx.x;
    if (n >= total) return;
    int xw = n % Wo; int t = n / Wo;
    int y  = t % Ho; int bc = t / Ho;
    const float* p = in + ((size_t)bc * Hi + 2 * y) * Wi + 2 * xw;
    out[n] = fmaxf(fmaxf(p[0], p[1]), fmaxf(p[Wi], p[Wi + 1]));
}

// ---------------------------------------------------------------------------
// Bilinear x2 upsample, align_corners=True, optional per-channel affine (BN),
// writes into channel-offset region of a concat buffer.
// ---------------------------------------------------------------------------
__global__ void up2_kernel(const float* __restrict__ in, float* __restrict__ out,
                           int C, int H, int W, int dstC, int coff,
                           const float* __restrict__ scale,
                           const float* __restrict__ shift)
{
    int Ho = 2 * H, Wo = 2 * W;
    long long total = (long long)4 * C * Ho * Wo;
    long long n = (long long)blockIdx.x * blockDim.x + threadIdx.x;
    if (n >= total) return;
    int ox = (int)(n % Wo); long long t = n / Wo;
    int oy = (int)(t % Ho); t /= Ho;
    int c  = (int)(t % C);  int b = (int)(t / C);

    float ry = (float)((double)(H - 1) / (double)(2 * H - 1));
    float rx = (float)((double)(W - 1) / (double)(2 * W - 1));
    float sy = (float)oy * ry;
    float sx = (float)ox * rx;
    int y0i = (int)sy;
    int x0i = (int)sx;
    float fy = sy - (float)y0i;
    float fx = sx - (float)x0i;
    int y1i = min(y0i + 1, H - 1);
    int x1i = min(x0i + 1, W - 1);

    const float* p = in + ((size_t)b * C + c) * H * W;
    float a0 = p[(size_t)y0i * W + x0i] * (1.f - fy) + p[(size_t)y1i * W + x0i] * fy;
    float a1 = p[(size_t)y0i * W + x1i] * (1.f - fy) + p[(size_t)y1i * W + x1i] * fy;
    float v  = a0 * (1.f - fx) + a1 * fx;
    if (scale) v = v * scale[c] + shift[c];
    out[((size_t)(b * dstC + coff + c) * Ho + oy) * Wo + ox] = v;
}

// ---------------------------------------------------------------------------
__global__ void concat_copy(const float4* __restrict__ src, float* __restrict__ dst,
                            int C, int HW, int dstC, int coff)
{
    int HW4 = HW >> 2;
    int total = 4 * C * HW4;
    int n = blockIdx.x * blockDim.x + threadIdx.x;
    if (n >= total) return;
    int i = n % HW4; int t = n / HW4;
    int c = t % C;   int b = t / C;
    ((float4*)(dst + (size_t)(b * dstC + coff + c) * HW))[i] = src[n];
}

// ---------------------------------------------------------------------------
// BatchNorm batch-stats over (B=4, H=32, W=32) per channel (512 channels),
// two-pass for accuracy; emits per-channel affine (scale, shift).
// ---------------------------------------------------------------------------
__global__ __launch_bounds__(256)
void bn_stats_kernel(const float* __restrict__ h, const float* __restrict__ g,
                     const float* __restrict__ be, float* __restrict__ scale,
                     float* __restrict__ shift)
{
    __shared__ float red[256];
    int c   = blockIdx.x;
    int tid = threadIdx.x;

    float s = 0.f;
    for (int b = 0; b < 4; b++) {
        const float* p = h + ((size_t)b * 512 + c) * 1024;
        for (int i = tid; i < 1024; i += 256) s += p[i];
    }
    red[tid] = s; __syncthreads();
    for (int o = 128; o > 0; o >>= 1) {
        if (tid < o) red[tid] += red[tid + o];
        __syncthreads();
    }
    float mean = red[0] * (1.f / 4096.f);
    __syncthreads();

    float q = 0.f;
    for (int b = 0; b < 4; b++) {
        const float* p = h + ((size_t)b * 512 + c) * 1024;
        for (int i = tid; i < 1024; i += 256) { float d = p[i] - mean; q += d * d; }
    }
    red[tid] = q; __syncthreads();
    for (int o = 128; o > 0; o >>= 1) {
        if (tid < o) red[tid] += red[tid + o];
        __syncthreads();
    }
    if (tid == 0) {
        float var = red[0] * (1.f / 4096.f);
        float sc  = g[c] * rsqrtf(var + 1e-5f);
        scale[c] = sc;
        shift[c] = be[c] - mean * sc;
    }
}

// ---------------------------------------------------------------------------
// Final 1x1 conv, Co=1, no activation. in:(4,32,256,256) -> out:(4,1,256,256)
// ---------------------------------------------------------------------------
__global__ void conv1x1_out(const float* __restrict__ in, const float* __restrict__ wl,
                            const float* __restrict__ bl, float* __restrict__ out)
{
    __shared__ float w[32];
    if (threadIdx.x < 32) w[threadIdx.x] = wl[threadIdx.x];
    __syncthreads();
    int n = blockIdx.x * blockDim.x + threadIdx.x;
    if (n >= 4 * 65536) return;
    int b = n >> 16;
    int i = n & 65535;
    const float* p = in + (size_t)b * 32 * 65536 + i;
    float s = bl[0];
#pragma unroll
    for (int c = 0; c < 32; c++) s = fmaf(p[(size_t)c * 65536], w[c], s);
    out[n] = s;
}

// ---------------------------------------------------------------------------
// Host side
// ---------------------------------------------------------------------------
static void conv3(const float* in, const float* wt, const float* bs, float* out,
                  int Ci, int HW, int Co)
{
    dim3 g((HW / 8) * (HW / 16), Co / 32, 4);
    conv_mish_kernel<3><<<g, 128>>>(in, wt, bs, out, Ci, HW, HW, Co, HW, HW, 1);
}

extern "C" void kernel_launch(void* const* d_in, const int* in_sizes, int n_in,
                              void* d_out, int out_size)
{
    const float* X    = (const float*)d_in[0];
    const float* W    = (const float*)d_in[1];
    const float* d1w  = (const float*)d_in[2];
    const float* d1b  = (const float*)d_in[3];
    const float* w2a  = (const float*)d_in[4];
    const float* b2a  = (const float*)d_in[5];
    const float* w2b  = (const float*)d_in[6];
    const float* b2b  = (const float*)d_in[7];
    const float* w3a  = (const float*)d_in[8];
    const float* b3a  = (const float*)d_in[9];
    const float* w3b  = (const float*)d_in[10];
    const float* b3b  = (const float*)d_in[11];
    const float* w4a  = (const float*)d_in[12];
    const float* b4a  = (const float*)d_in[13];
    const float* w4b  = (const float*)d_in[14];
    const float* b4b  = (const float*)d_in[15];
    const float* g4   = (const float*)d_in[16];
    const float* be4  = (const float*)d_in[17];
    const float* u3a  = (const float*)d_in[18];
    const float* ub3a = (const float*)d_in[19];
    const float* u3b  = (const float*)d_in[20];
    const float* ub3b = (const float*)d_in[21];
    const float* u2a  = (const float*)d_in[22];
    const float* ub2a = (const float*)d_in[23];
    const float* u2b  = (const float*)d_in[24];
    const float* ub2b = (const float*)d_in[25];
    const float* u1a  = (const float*)d_in[26];
    const float* ub1a = (const float*)d_in[27];
    const float* u1b  = (const float*)d_in[28];
    const float* ub1b = (const float*)d_in[29];
    const float* wl   = (const float*)d_in[30];
    const float* bl   = (const float*)d_in[31];

    void *pa, *pb, *pc1, *pc2, *pc3, *pbs, *pbb;
    cudaGetSymbolAddress(&pa,  g_SA);
    cudaGetSymbolAddress(&pb,  g_SB);
    cudaGetSymbolAddress(&pc1, g_C1);
    cudaGetSymbolAddress(&pc2, g_C2);
    cudaGetSymbolAddress(&pc3, g_C3);
    cudaGetSymbolAddress(&pbs, g_BNscale);
    cudaGetSymbolAddress(&pbb, g_BNshift);
    float* SA  = (float*)pa;
    float* SB  = (float*)pb;
    float* C1  = (float*)pc1;
    float* C2  = (float*)pc2;
    float* C3  = (float*)pc3;
    float* BNS = (float*)pbs;
    float* BNB = (float*)pbb;

    // --- Encoder ---
    // dyn conv (per-sample) + mish -> SA (4,32,255,255)
    dyn_conv_mish<<<dim3(16, 16, 4), 256>>>(X, W, SA);

    // d1: K=4, pad=2, 255->256 + mish -> C1 (4,32,256,256)
    {
        dim3 g((256 / 8) * (256 / 16), 1, 4);
        conv_mish_kernel<4><<<g, 128>>>(SA, d1w, d1b, C1, 32, 255, 255, 32, 256, 256, 2);
    }

    // pool C1 -> SB (4,32,128,128)
    maxpool_kernel<<<cdiv(4 * 32 * 128 * 128, 256), 256>>>(C1, SB, 4 * 32, 256, 256);

    conv3(SB, w2a, b2a, SA, 32, 128, 128);     // SA = t2
    conv3(SA, w2b, b2b, C2, 128, 128, 128);    // C2

    maxpool_kernel<<<cdiv(4 * 128 * 64 * 64, 256), 256>>>(C2, SA, 4 * 128, 128, 128);

    conv3(SA, w3a, b3a, SB, 128, 64, 256);     // SB = t3
    conv3(SB, w3b, b3b, C3, 256, 64, 256);     // C3

    maxpool_kernel<<<cdiv(4 * 256 * 32 * 32, 256), 256>>>(C3, SA, 4 * 256, 64, 64);

    conv3(SA, w4a, b4a, SB, 256, 32, 512);     // SB = t4
    conv3(SB, w4b, b4b, SA, 512, 32, 512);     // SA = h (pre-BN)

    // --- Bottleneck BN (as per-channel affine, fused into upsample) ---
    bn_stats_kernel<<<512, 256>>>(SA, g4, be4, BNS, BNB);

    // --- Decoder ---
    // up2(bn(h)) -> SB[:,0:512] of cat3 (4,768,64,64); concat C3
    up2_kernel<<<cdiv(4 * 512 * 64 * 64, 256), 256>>>(SA, SB, 512, 32, 32, 768, 0, BNS, BNB);
    concat_copy<<<cdiv(4 * 256 * (64 * 64 / 4), 256), 256>>>((const float4*)C3, SB, 256, 64 * 64, 768, 512);

    conv3(SB, u3a, ub3a, SA, 768, 64, 256);    // SA = t5
    conv3(SA, u3b, ub3b, SB, 256, 64, 256);    // SB = u3

    up2_kernel<<<cdiv(4 * 256 * 128 * 128, 256), 256>>>(SB, SA, 256, 64, 64, 384, 0, nullptr, nullptr);
    concat_copy<<<cdiv(4 * 128 * (128 * 128 / 4), 256), 256>>>((const float4*)C2, SA, 128, 128 * 128, 384, 256);

    conv3(SA, u2a, ub2a, SB, 384, 128, 128);   // SB = t6
    conv3(SB, u2b, ub2b, SA, 128, 128, 128);   // SA = u2

    up2_kernel<<<cdiv(4 * 128 * 256 * 256, 256), 256>>>(SA, SB, 128, 128, 128, 160, 0, nullptr, nullptr);
    concat_copy<<<cdiv(4 * 32 * (256 * 256 / 4), 256), 256>>>((const float4*)C1, SB, 32, 256 * 256, 160, 128);

    conv3(SB, u1a, ub1a, SA, 160, 256, 32);    // SA = t7
    conv3(SA, u1b, ub1b, SB, 32, 256, 32);     // SB = u1

    // final 1x1 conv -> d_out
    conv1x1_out<<<cdiv(4 * 65536, 256), 256>>>(SB, wl, bl, (float*)d_out);
}